// round 1
// baseline (speedup 1.0000x reference)
#include <cuda_runtime.h>
#include <math.h>

#define NN   30000
#define EE   480000
#define HH   128
#define NFF  4
#define NMM  8
#define TT   4
#define DMID 8
#define KCAT 132
#define KC   64
#define EPSF 1e-5f
#define DTF  0.1f

// ---------------- scratch (static device memory; no allocations) ----------------
__device__ int   g_cnt[NN];
__device__ float g_dinv[NN];
__device__ int   g_rowptr[NN + 1];
__device__ int   g_cursor[NN];
__device__ int   g_src[EE];
__device__ float g_x[NN * HH];
__device__ float g_z[NN * HH];
__device__ float g_xcat[NN * KCAT];   // [aggF(4) | agg_mesh(128)]
__device__ float g_small[NN * NMM];   // aggregated meshfield (8 cols)
__device__ float g_F[NN * NFF];
__device__ float g_h4[NN * NFF];
__device__ float g_stats[2 * HH];

// ---------------- graph normalization + CSR build ----------------
__global__ void k_zero_cnt() {
    int i = blockIdx.x * blockDim.x + threadIdx.x;
    if (i < NN) g_cnt[i] = 0;
}
__global__ void k_count(const int* __restrict__ ei) {
    int e = blockIdx.x * blockDim.x + threadIdx.x;
    if (e < EE) atomicAdd(&g_cnt[ei[EE + e]], 1);
}
__global__ void k_dinv() {
    int i = blockIdx.x * blockDim.x + threadIdx.x;
    if (i < NN) g_dinv[i] = rsqrtf((float)g_cnt[i] + 1.0f);  // deg includes self loop
}
__global__ void k_scan() {
    __shared__ int partial[1024];
    const int CH = (NN + 1023) / 1024;
    int tid = threadIdx.x;
    int base = tid * CH;
    int s = 0;
    for (int j = 0; j < CH; j++) {
        int idx = base + j;
        if (idx < NN) s += g_cnt[idx];
    }
    partial[tid] = s;
    __syncthreads();
    if (tid == 0) {
        int run = 0;
        for (int i = 0; i < 1024; i++) { int v = partial[i]; partial[i] = run; run += v; }
    }
    __syncthreads();
    int run = partial[tid];
    for (int j = 0; j < CH; j++) {
        int idx = base + j;
        if (idx < NN) {
            g_rowptr[idx] = run;
            g_cursor[idx] = run;
            run += g_cnt[idx];
        }
    }
    if (tid == 1023) g_rowptr[NN] = run;  // == EE
}
__global__ void k_fill(const int* __restrict__ ei) {
    int e = blockIdx.x * blockDim.x + threadIdx.x;
    if (e < EE) {
        int d = ei[EE + e];
        int p = atomicAdd(&g_cursor[d], 1);
        g_src[p] = ei[e];
    }
}

// ---------------- aggregation kernels  y = D^-1/2 (A+I) D^-1/2 x ----------------
// 128-column: one block (128 thr) per node; optional relu applied on load.
template <bool RELU>
__global__ void k_agg128(const float* __restrict__ in, float* __restrict__ out,
                         int ostride, int ooff) {
    int i = blockIdx.x;
    int c = threadIdx.x;
    float di = g_dinv[i];
    float v = in[(size_t)i * HH + c];
    if (RELU) v = fmaxf(v, 0.0f);
    float acc = di * di * v;
    int e = g_rowptr[i], end = g_rowptr[i + 1];
    for (; e + 4 <= end; e += 4) {
        int s0 = g_src[e], s1 = g_src[e + 1], s2 = g_src[e + 2], s3 = g_src[e + 3];
        float w0 = g_dinv[s0] * di, w1 = g_dinv[s1] * di;
        float w2 = g_dinv[s2] * di, w3 = g_dinv[s3] * di;
        float v0 = in[(size_t)s0 * HH + c];
        float v1 = in[(size_t)s1 * HH + c];
        float v2 = in[(size_t)s2 * HH + c];
        float v3 = in[(size_t)s3 * HH + c];
        if (RELU) {
            v0 = fmaxf(v0, 0.f); v1 = fmaxf(v1, 0.f);
            v2 = fmaxf(v2, 0.f); v3 = fmaxf(v3, 0.f);
        }
        acc += w0 * v0; acc += w1 * v1; acc += w2 * v2; acc += w3 * v3;
    }
    for (; e < end; e++) {
        int s = g_src[e];
        float v4 = in[(size_t)s * HH + c];
        if (RELU) v4 = fmaxf(v4, 0.f);
        acc += g_dinv[s] * di * v4;
    }
    out[(size_t)i * ostride + ooff + c] = acc;
}

// 8-column aggregate of meshfield -> g_small
__global__ void k_agg8(const float* __restrict__ in) {
    int i = blockIdx.x * blockDim.x + threadIdx.x;
    if (i >= NN) return;
    float di = g_dinv[i];
    const float4* inv = (const float4*)in;
    float4 u0 = inv[i * 2], u1 = inv[i * 2 + 1];
    float w = di * di;
    float a0 = w * u0.x, a1 = w * u0.y, a2 = w * u0.z, a3 = w * u0.w;
    float a4 = w * u1.x, a5 = w * u1.y, a6 = w * u1.z, a7 = w * u1.w;
    for (int e = g_rowptr[i]; e < g_rowptr[i + 1]; e++) {
        int s = g_src[e];
        float ww = g_dinv[s] * di;
        float4 b0 = inv[s * 2], b1 = inv[s * 2 + 1];
        a0 += ww * b0.x; a1 += ww * b0.y; a2 += ww * b0.z; a3 += ww * b0.w;
        a4 += ww * b1.x; a5 += ww * b1.y; a6 += ww * b1.z; a7 += ww * b1.w;
    }
    float4* ov = (float4*)g_small;
    ov[i * 2]     = make_float4(a0, a1, a2, a3);
    ov[i * 2 + 1] = make_float4(a4, a5, a6, a7);
}

// 4-column aggregate of F_cur -> xcat columns [0,4)
__global__ void k_aggF() {
    int i = blockIdx.x * blockDim.x + threadIdx.x;
    if (i >= NN) return;
    float di = g_dinv[i];
    const float4* Fv = (const float4*)g_F;
    float4 f = Fv[i];
    float w = di * di;
    float a0 = w * f.x, a1 = w * f.y, a2 = w * f.z, a3 = w * f.w;
    for (int e = g_rowptr[i]; e < g_rowptr[i + 1]; e++) {
        int s = g_src[e];
        float ww = g_dinv[s] * di;
        float4 u = Fv[s];
        a0 += ww * u.x; a1 += ww * u.y; a2 += ww * u.z; a3 += ww * u.w;
    }
    *(float4*)(g_xcat + (size_t)i * KCAT) = make_float4(a0, a1, a2, a3);
}

// ---------------- GEMM: out[N,128] = x[N,K] @ W[K,128] + bias (opt tanh) ----------
// 64x128 block tile, 256 threads, 8x4 register tile, K chunked by 64.
template <int ACT>  // 0 none, 1 tanh
__global__ void k_gemm128(const float* __restrict__ x, int K,
                          const float* __restrict__ W, const float* __restrict__ bias,
                          float* __restrict__ out) {
    __shared__ float xs[64 * KC];
    __shared__ float ws[KC * HH];
    int tid = threadIdx.x;
    int row0 = blockIdx.x * 64;
    int valid = NN - row0; if (valid > 64) valid = 64;
    int tx = tid & 31, ty = tid >> 5;

    float acc[8][4];
#pragma unroll
    for (int i = 0; i < 8; i++)
#pragma unroll
        for (int j = 0; j < 4; j++) acc[i][j] = 0.0f;

    for (int k0 = 0; k0 < K; k0 += KC) {
        int kc = K - k0; if (kc > KC) kc = KC;
        __syncthreads();
        // load W chunk (kc x 128), float4 coalesced
        {
            const float4* Wv = (const float4*)(W + (size_t)k0 * HH);
            float4* wv = (float4*)ws;
            for (int idx = tid; idx < kc * 32; idx += 256) wv[idx] = Wv[idx];
        }
        // load x chunk (valid x kc)
        {
            const float* xg = x + (size_t)row0 * K + k0;
            for (int idx = tid; idx < valid * kc; idx += 256) {
                int r = idx / kc, j = idx - r * kc;
                xs[r * KC + j] = xg[(size_t)r * K + j];
            }
        }
        __syncthreads();
        const float* xsr = xs + (ty * 8) * KC;
        for (int j = 0; j < kc; j++) {
            float4 b = *(const float4*)&ws[j * HH + tx * 4];
#pragma unroll
            for (int i = 0; i < 8; i++) {
                float a = xsr[i * KC + j];
                acc[i][0] += a * b.x; acc[i][1] += a * b.y;
                acc[i][2] += a * b.z; acc[i][3] += a * b.w;
            }
        }
    }
    float4 bv = *(const float4*)&bias[tx * 4];
#pragma unroll
    for (int i = 0; i < 8; i++) {
        int r = ty * 8 + i;
        if (row0 + r < NN) {
            float o0 = acc[i][0] + bv.x, o1 = acc[i][1] + bv.y;
            float o2 = acc[i][2] + bv.z, o3 = acc[i][3] + bv.w;
            if (ACT == 1) { o0 = tanhf(o0); o1 = tanhf(o1); o2 = tanhf(o2); o3 = tanhf(o3); }
            *(float4*)&out[(size_t)(row0 + r) * HH + tx * 4] = make_float4(o0, o1, o2, o3);
        }
    }
}

// small GEMM: g_h4[N,4] = x[N,128] @ W[128,4] (no bias; bias added in final agg)
__global__ void k_gemm_to4(const float* __restrict__ x, const float* __restrict__ W) {
    __shared__ float xs[32 * 129];
    __shared__ float ws[HH * 4];
    int tid = threadIdx.x;
    int row0 = blockIdx.x * 32;
    int valid = NN - row0; if (valid > 32) valid = 32;
    for (int idx = tid; idx < HH * 4; idx += 128) ws[idx] = W[idx];
    for (int idx = tid; idx < valid * HH; idx += 128) {
        int r = idx >> 7, k = idx & 127;
        xs[r * 129 + k] = x[(size_t)row0 * HH + idx];
    }
    __syncthreads();
    int r = tid >> 2, c = tid & 3;
    if (row0 + r < NN) {
        float acc = 0.0f;
#pragma unroll 8
        for (int k = 0; k < HH; k++) acc += xs[r * 129 + k] * ws[k * 4 + c];
        g_h4[(size_t)(row0 + r) * 4 + c] = acc;
    }
}

// ---------------- instance norm (per-channel over nodes) ----------------
__global__ void k_zero_stats() { g_stats[threadIdx.x] = 0.0f; }
__global__ void k_in_stats(const float* __restrict__ x) {
    int c = threadIdx.x;
    float s = 0.0f, q = 0.0f;
    for (int r = blockIdx.x; r < NN; r += gridDim.x) {
        float v = x[(size_t)r * HH + c];
        s += v; q += v * v;
    }
    atomicAdd(&g_stats[c], s);
    atomicAdd(&g_stats[HH + c], q);
}
__global__ void k_in_apply(float* __restrict__ x) {
    int idx = blockIdx.x * blockDim.x + threadIdx.x;
    if (idx >= NN * HH) return;
    int c = idx & (HH - 1);
    const float invn = 1.0f / (float)NN;
    float m = g_stats[c] * invn;
    float var = g_stats[HH + c] * invn - m * m;
    x[idx] = (x[idx] - m) * rsqrtf(var + EPSF);
}

// ---------------- recurrent step tail ----------------
__global__ void k_copyF0(const float* __restrict__ F0) {
    int i = blockIdx.x * blockDim.x + threadIdx.x;
    if (i < NN * NFF) g_F[i] = F0[i];
}
__global__ void k_step_final(const float* __restrict__ b9, float* __restrict__ out, int t) {
    int i = blockIdx.x * blockDim.x + threadIdx.x;
    if (i >= NN) return;
    float di = g_dinv[i];
    const float4* h4 = (const float4*)g_h4;
    float4 v = h4[i];
    float w = di * di;
    float a0 = b9[0] + w * v.x, a1 = b9[1] + w * v.y;
    float a2 = b9[2] + w * v.z, a3 = b9[3] + w * v.w;
    for (int e = g_rowptr[i]; e < g_rowptr[i + 1]; e++) {
        int s = g_src[e];
        float ww = g_dinv[s] * di;
        float4 u = h4[s];
        a0 += ww * u.x; a1 += ww * u.y; a2 += ww * u.z; a3 += ww * u.w;
    }
    float d0 = tanhf(a0), d1 = tanhf(a1), d2 = tanhf(a2), d3 = tanhf(a3);
    float4 f = ((float4*)g_F)[i];
    float n0 = tanhf(f.x + DTF * d0), n1 = tanhf(f.y + DTF * d1);
    float n2 = tanhf(f.z + DTF * d2), n3 = tanhf(f.w + DTF * d3);
    ((float4*)g_F)[i] = make_float4(n0, n1, n2, n3);
    int ob = i * TT * NFF + t * NFF;
    out[ob + 0] = n0; out[ob + 1] = n1; out[ob + 2] = n2; out[ob + 3] = n3;
    int ob2 = NN * TT * NFF + ob;
    out[ob2 + 0] = d0; out[ob2 + 1] = d1; out[ob2 + 2] = d2; out[ob2 + 3] = d3;
}

// ---------------- host orchestration ----------------
static void instnorm(float* x) {
    k_zero_stats<<<1, 2 * HH>>>();
    k_in_stats<<<512, HH>>>(x);
    k_in_apply<<<(NN * HH + 255) / 256, 256>>>(x);
}

extern "C" void kernel_launch(void* const* d_in, const int* in_sizes, int n_in,
                              void* d_out, int out_size) {
    const float* F0        = (const float*)d_in[0];
    const int*   ei        = (const int*)d_in[1];
    const float* meshfield = (const float*)d_in[2];
    int w = (n_in >= 16 && in_sizes[3] == 1) ? 4 : 3;  // skip scalar n_time if present
    const float* mesh_W0 = (const float*)d_in[w + 0];
    const float* mesh_b0 = (const float*)d_in[w + 1];
    const float* mesh_Wh = (const float*)d_in[w + 2];
    const float* mesh_bh = (const float*)d_in[w + 3];
    const float* mesh_W9 = (const float*)d_in[w + 4];
    const float* mesh_b9 = (const float*)d_in[w + 5];
    const float* diff_W0 = (const float*)d_in[w + 6];
    const float* diff_b0 = (const float*)d_in[w + 7];
    const float* diff_Wh = (const float*)d_in[w + 8];
    const float* diff_bh = (const float*)d_in[w + 9];
    const float* diff_W9 = (const float*)d_in[w + 10];
    const float* diff_b9 = (const float*)d_in[w + 11];
    float* out = (float*)d_out;

    float *px, *pz, *pxcat, *psmall;
    cudaGetSymbolAddress((void**)&px, g_x);
    cudaGetSymbolAddress((void**)&pz, g_z);
    cudaGetSymbolAddress((void**)&pxcat, g_xcat);
    cudaGetSymbolAddress((void**)&psmall, g_small);

    const int GB = (NN + 63) / 64;  // gemm blocks

    // --- graph normalization + CSR ---
    k_zero_cnt<<<(NN + 255) / 256, 256>>>();
    k_count<<<(EE + 255) / 256, 256>>>(ei);
    k_dinv<<<(NN + 255) / 256, 256>>>();
    k_scan<<<1, 1024>>>();
    k_fill<<<(EE + 255) / 256, 256>>>(ei);

    // --- mesh descriptor block ---
    k_agg8<<<(NN + 127) / 128, 128>>>(meshfield);                      // z = A@meshfield (8 cols)
    k_gemm128<0><<<GB, 256>>>(psmall, NMM, mesh_W0, mesh_b0, px);      // conv0
    instnorm(px);
    for (int l = 0; l < DMID; l++) {
        k_agg128<true><<<NN, HH>>>(px, pz, HH, 0);                     // A@relu(x)
        k_gemm128<0><<<GB, 256>>>(pz, HH, mesh_Wh + (size_t)l * HH * HH,
                                  mesh_bh + (size_t)l * HH, px);
    }
    k_agg128<false><<<NN, HH>>>(px, pz, HH, 0);                        // conv9
    k_gemm128<1><<<GB, 256>>>(pz, HH, mesh_W9, mesh_b9, px);           // tanh -> mesh latent
    k_agg128<false><<<NN, HH>>>(px, pxcat, KCAT, NFF);                 // agg_mesh -> xcat[:,4:132] (time-invariant)

    // --- recurrent differentiator ---
    k_copyF0<<<(NN * NFF + 255) / 256, 256>>>(F0);
    for (int t = 0; t < TT; t++) {
        k_aggF<<<(NN + 127) / 128, 128>>>();                           // xcat[:,0:4] = A@F
        k_gemm128<0><<<GB, 256>>>(pxcat, KCAT, diff_W0, diff_b0, px);  // conv0 (K=132)
        instnorm(px);
        for (int l = 0; l < DMID; l++) {
            k_agg128<true><<<NN, HH>>>(px, pz, HH, 0);
            k_gemm128<0><<<GB, 256>>>(pz, HH, diff_Wh + (size_t)l * HH * HH,
                                      diff_bh + (size_t)l * HH, px);
        }
        k_gemm_to4<<<(NN + 31) / 32, 128>>>(px, diff_W9);              // x @ W9 -> h4
        k_step_final<<<(NN + 127) / 128, 128>>>(diff_b9, out, t);      // A@h4+b9, tanh, Euler, write
    }
    (void)out_size;
}

// round 2
// speedup vs baseline: 1.2986x; 1.2986x over previous
#include <cuda_runtime.h>
#include <math.h>

#define NN   30000
#define EE   480000
#define HH   128
#define NFF  4
#define NMM  8
#define TT   4
#define DMID 8
#define KCAT 132
#define KC   64
#define BM   64          // fused tile: nodes per block
#define EPSF 1e-5f
#define DTF  0.1f

// ---------------- scratch (static device memory; no allocations) ----------------
__device__ int   g_cnt[NN];
__device__ float g_dinv[NN];
__device__ int   g_rowptr[NN + 1];
__device__ int   g_cursor[NN];
__device__ int   g_src[EE];
__device__ float g_x[NN * HH];
__device__ float g_z[NN * HH];
__device__ float g_xcat[NN * KCAT];   // [aggF(4) | agg_mesh(128)]
__device__ float g_small[NN * NMM];   // aggregated meshfield (8 cols)
__device__ float g_F[NN * NFF];
__device__ float g_h4[NN * NFF];
__device__ float g_stats[2 * HH];

// ---------------- graph normalization + CSR build ----------------
__global__ void k_zero_cnt() {
    int i = blockIdx.x * blockDim.x + threadIdx.x;
    if (i < NN) g_cnt[i] = 0;
}
__global__ void k_count(const int* __restrict__ ei) {
    int e = blockIdx.x * blockDim.x + threadIdx.x;
    if (e < EE) atomicAdd(&g_cnt[ei[EE + e]], 1);
}
__global__ void k_dinv() {
    int i = blockIdx.x * blockDim.x + threadIdx.x;
    if (i < NN) g_dinv[i] = rsqrtf((float)g_cnt[i] + 1.0f);  // deg includes self loop
}
__global__ void k_scan() {
    __shared__ int partial[1024];
    const int CH = (NN + 1023) / 1024;
    int tid = threadIdx.x;
    int base = tid * CH;
    int s = 0;
    for (int j = 0; j < CH; j++) {
        int idx = base + j;
        if (idx < NN) s += g_cnt[idx];
    }
    partial[tid] = s;
    __syncthreads();
    // Hillis-Steele inclusive scan over 1024 partials
    for (int off = 1; off < 1024; off <<= 1) {
        int v = (tid >= off) ? partial[tid - off] : 0;
        __syncthreads();
        partial[tid] += v;
        __syncthreads();
    }
    int run = partial[tid] - s;  // exclusive prefix
    for (int j = 0; j < CH; j++) {
        int idx = base + j;
        if (idx < NN) {
            g_rowptr[idx] = run;
            g_cursor[idx] = run;
            run += g_cnt[idx];
        }
    }
    if (tid == 1023) g_rowptr[NN] = partial[1023];  // == EE
}
__global__ void k_fill(const int* __restrict__ ei) {
    int e = blockIdx.x * blockDim.x + threadIdx.x;
    if (e < EE) {
        int d = ei[EE + e];
        int p = atomicAdd(&g_cursor[d], 1);
        g_src[p] = ei[e];
    }
}

// ---------------- FUSED agg(+relu) -> GEMM(K=128) (+bias, opt tanh) ----------------
// Phase A: 8 warps gather 64 node rows (A @ act(x)) into smem.
// Phase B: 64x128 GEMM from smem against W[128,128] streamed in BK=8 chunks.
template <bool RELU, int ACT>  // ACT: 0 none, 1 tanh
__global__ void __launch_bounds__(256)
k_fused(const float* __restrict__ in, const float* __restrict__ W,
        const float* __restrict__ bias, float* __restrict__ out) {
    __shared__ float zs[BM * HH];      // 32 KB
    __shared__ float ws[8 * HH];       // 4 KB

    int tid = threadIdx.x;
    int lane = tid & 31, wrp = tid >> 5;
    int row0 = blockIdx.x * BM;

    // ---- Phase A: gather ----
    for (int mi = 0; mi < 8; mi++) {
        int m = wrp * 8 + mi;
        int i = row0 + m;
        if (i >= NN) break;
        float di = g_dinv[i];
        float4 v = *(const float4*)&in[(size_t)i * HH + lane * 4];
        if (RELU) { v.x = fmaxf(v.x, 0.f); v.y = fmaxf(v.y, 0.f);
                    v.z = fmaxf(v.z, 0.f); v.w = fmaxf(v.w, 0.f); }
        float w = di * di;
        float a0 = w * v.x, a1 = w * v.y, a2 = w * v.z, a3 = w * v.w;
        int e = g_rowptr[i], end = g_rowptr[i + 1];
        for (; e + 2 <= end; e += 2) {
            int s0 = g_src[e], s1 = g_src[e + 1];
            float w0 = g_dinv[s0] * di, w1 = g_dinv[s1] * di;
            float4 u0 = *(const float4*)&in[(size_t)s0 * HH + lane * 4];
            float4 u1 = *(const float4*)&in[(size_t)s1 * HH + lane * 4];
            if (RELU) {
                u0.x = fmaxf(u0.x, 0.f); u0.y = fmaxf(u0.y, 0.f);
                u0.z = fmaxf(u0.z, 0.f); u0.w = fmaxf(u0.w, 0.f);
                u1.x = fmaxf(u1.x, 0.f); u1.y = fmaxf(u1.y, 0.f);
                u1.z = fmaxf(u1.z, 0.f); u1.w = fmaxf(u1.w, 0.f);
            }
            a0 += w0 * u0.x; a1 += w0 * u0.y; a2 += w0 * u0.z; a3 += w0 * u0.w;
            a0 += w1 * u1.x; a1 += w1 * u1.y; a2 += w1 * u1.z; a3 += w1 * u1.w;
        }
        if (e < end) {
            int s = g_src[e];
            float w2 = g_dinv[s] * di;
            float4 u = *(const float4*)&in[(size_t)s * HH + lane * 4];
            if (RELU) {
                u.x = fmaxf(u.x, 0.f); u.y = fmaxf(u.y, 0.f);
                u.z = fmaxf(u.z, 0.f); u.w = fmaxf(u.w, 0.f);
            }
            a0 += w2 * u.x; a1 += w2 * u.y; a2 += w2 * u.z; a3 += w2 * u.w;
        }
        *(float4*)&zs[m * HH + lane * 4] = make_float4(a0, a1, a2, a3);
    }

    // ---- Phase B: GEMM zs[64,128] @ W[128,128] ----
    int tx = tid & 31, ty = tid >> 5;
    float acc[8][4];
#pragma unroll
    for (int i = 0; i < 8; i++)
#pragma unroll
        for (int j = 0; j < 4; j++) acc[i][j] = 0.0f;

    const float* zrow = zs + (ty * 8) * HH;
#pragma unroll 1
    for (int k0 = 0; k0 < HH; k0 += 8) {
        __syncthreads();
        // load 8x128 chunk of W: one float4 per thread
        *(float4*)&ws[(tid >> 5) * HH + (tid & 31) * 4] =
            *(const float4*)&W[(size_t)(k0 + (tid >> 5)) * HH + (tid & 31) * 4];
        __syncthreads();
#pragma unroll
        for (int kk = 0; kk < 8; kk++) {
            float4 b = *(const float4*)&ws[kk * HH + tx * 4];
#pragma unroll
            for (int i = 0; i < 8; i++) {
                float a = zrow[i * HH + k0 + kk];
                acc[i][0] += a * b.x; acc[i][1] += a * b.y;
                acc[i][2] += a * b.z; acc[i][3] += a * b.w;
            }
        }
    }
    float4 bv = *(const float4*)&bias[tx * 4];
#pragma unroll
    for (int i = 0; i < 8; i++) {
        int r = row0 + ty * 8 + i;
        if (r < NN) {
            float o0 = acc[i][0] + bv.x, o1 = acc[i][1] + bv.y;
            float o2 = acc[i][2] + bv.z, o3 = acc[i][3] + bv.w;
            if (ACT == 1) { o0 = tanhf(o0); o1 = tanhf(o1); o2 = tanhf(o2); o3 = tanhf(o3); }
            *(float4*)&out[(size_t)r * HH + tx * 4] = make_float4(o0, o1, o2, o3);
        }
    }
}

// ---------------- standalone 128-col aggregation (used once for xcat mesh cols) ----
template <bool RELU>
__global__ void k_agg128(const float* __restrict__ in, float* __restrict__ out,
                         int ostride, int ooff) {
    int i = blockIdx.x;
    int c = threadIdx.x;
    float di = g_dinv[i];
    float v = in[(size_t)i * HH + c];
    if (RELU) v = fmaxf(v, 0.0f);
    float acc = di * di * v;
    int e = g_rowptr[i], end = g_rowptr[i + 1];
    for (; e + 4 <= end; e += 4) {
        int s0 = g_src[e], s1 = g_src[e + 1], s2 = g_src[e + 2], s3 = g_src[e + 3];
        float w0 = g_dinv[s0] * di, w1 = g_dinv[s1] * di;
        float w2 = g_dinv[s2] * di, w3 = g_dinv[s3] * di;
        float v0 = in[(size_t)s0 * HH + c];
        float v1 = in[(size_t)s1 * HH + c];
        float v2 = in[(size_t)s2 * HH + c];
        float v3 = in[(size_t)s3 * HH + c];
        if (RELU) {
            v0 = fmaxf(v0, 0.f); v1 = fmaxf(v1, 0.f);
            v2 = fmaxf(v2, 0.f); v3 = fmaxf(v3, 0.f);
        }
        acc += w0 * v0; acc += w1 * v1; acc += w2 * v2; acc += w3 * v3;
    }
    for (; e < end; e++) {
        int s = g_src[e];
        float v4 = in[(size_t)s * HH + c];
        if (RELU) v4 = fmaxf(v4, 0.f);
        acc += g_dinv[s] * di * v4;
    }
    out[(size_t)i * ostride + ooff + c] = acc;
}

// 8-column aggregate of meshfield -> g_small
__global__ void k_agg8(const float* __restrict__ in) {
    int i = blockIdx.x * blockDim.x + threadIdx.x;
    if (i >= NN) return;
    float di = g_dinv[i];
    const float4* inv = (const float4*)in;
    float4 u0 = inv[i * 2], u1 = inv[i * 2 + 1];
    float w = di * di;
    float a0 = w * u0.x, a1 = w * u0.y, a2 = w * u0.z, a3 = w * u0.w;
    float a4 = w * u1.x, a5 = w * u1.y, a6 = w * u1.z, a7 = w * u1.w;
    for (int e = g_rowptr[i]; e < g_rowptr[i + 1]; e++) {
        int s = g_src[e];
        float ww = g_dinv[s] * di;
        float4 b0 = inv[s * 2], b1 = inv[s * 2 + 1];
        a0 += ww * b0.x; a1 += ww * b0.y; a2 += ww * b0.z; a3 += ww * b0.w;
        a4 += ww * b1.x; a5 += ww * b1.y; a6 += ww * b1.z; a7 += ww * b1.w;
    }
    float4* ov = (float4*)g_small;
    ov[i * 2]     = make_float4(a0, a1, a2, a3);
    ov[i * 2 + 1] = make_float4(a4, a5, a6, a7);
}

// 4-column aggregate of F_cur -> xcat columns [0,4)
__global__ void k_aggF() {
    int i = blockIdx.x * blockDim.x + threadIdx.x;
    if (i >= NN) return;
    float di = g_dinv[i];
    const float4* Fv = (const float4*)g_F;
    float4 f = Fv[i];
    float w = di * di;
    float a0 = w * f.x, a1 = w * f.y, a2 = w * f.z, a3 = w * f.w;
    for (int e = g_rowptr[i]; e < g_rowptr[i + 1]; e++) {
        int s = g_src[e];
        float ww = g_dinv[s] * di;
        float4 u = Fv[s];
        a0 += ww * u.x; a1 += ww * u.y; a2 += ww * u.z; a3 += ww * u.w;
    }
    *(float4*)(g_xcat + (size_t)i * KCAT) = make_float4(a0, a1, a2, a3);
}

// ---------------- generic GEMM: out[N,128] = x[N,K] @ W[K,128] + bias ----------
template <int ACT>  // 0 none, 1 tanh
__global__ void k_gemm128(const float* __restrict__ x, int K,
                          const float* __restrict__ W, const float* __restrict__ bias,
                          float* __restrict__ out) {
    __shared__ float xs[64 * KC];
    __shared__ float ws[KC * HH];
    int tid = threadIdx.x;
    int row0 = blockIdx.x * 64;
    int valid = NN - row0; if (valid > 64) valid = 64;
    int tx = tid & 31, ty = tid >> 5;

    float acc[8][4];
#pragma unroll
    for (int i = 0; i < 8; i++)
#pragma unroll
        for (int j = 0; j < 4; j++) acc[i][j] = 0.0f;

    for (int k0 = 0; k0 < K; k0 += KC) {
        int kc = K - k0; if (kc > KC) kc = KC;
        __syncthreads();
        {
            const float4* Wv = (const float4*)(W + (size_t)k0 * HH);
            float4* wv = (float4*)ws;
            for (int idx = tid; idx < kc * 32; idx += 256) wv[idx] = Wv[idx];
        }
        {
            const float* xg = x + (size_t)row0 * K + k0;
            for (int idx = tid; idx < valid * kc; idx += 256) {
                int r = idx / kc, j = idx - r * kc;
                xs[r * KC + j] = xg[(size_t)r * K + j];
            }
        }
        __syncthreads();
        const float* xsr = xs + (ty * 8) * KC;
        for (int j = 0; j < kc; j++) {
            float4 b = *(const float4*)&ws[j * HH + tx * 4];
#pragma unroll
            for (int i = 0; i < 8; i++) {
                float a = xsr[i * KC + j];
                acc[i][0] += a * b.x; acc[i][1] += a * b.y;
                acc[i][2] += a * b.z; acc[i][3] += a * b.w;
            }
        }
    }
    float4 bv = *(const float4*)&bias[tx * 4];
#pragma unroll
    for (int i = 0; i < 8; i++) {
        int r = ty * 8 + i;
        if (row0 + r < NN) {
            float o0 = acc[i][0] + bv.x, o1 = acc[i][1] + bv.y;
            float o2 = acc[i][2] + bv.z, o3 = acc[i][3] + bv.w;
            if (ACT == 1) { o0 = tanhf(o0); o1 = tanhf(o1); o2 = tanhf(o2); o3 = tanhf(o3); }
            *(float4*)&out[(size_t)(row0 + r) * HH + tx * 4] = make_float4(o0, o1, o2, o3);
        }
    }
}

// small GEMM: g_h4[N,4] = x[N,128] @ W[128,4]
__global__ void k_gemm_to4(const float* __restrict__ x, const float* __restrict__ W) {
    __shared__ float xs[32 * 129];
    __shared__ float ws[HH * 4];
    int tid = threadIdx.x;
    int row0 = blockIdx.x * 32;
    int valid = NN - row0; if (valid > 32) valid = 32;
    for (int idx = tid; idx < HH * 4; idx += 128) ws[idx] = W[idx];
    for (int idx = tid; idx < valid * HH; idx += 128) {
        int r = idx >> 7, k = idx & 127;
        xs[r * 129 + k] = x[(size_t)row0 * HH + idx];
    }
    __syncthreads();
    int r = tid >> 2, c = tid & 3;
    if (row0 + r < NN) {
        float acc = 0.0f;
#pragma unroll 8
        for (int k = 0; k < HH; k++) acc += xs[r * 129 + k] * ws[k * 4 + c];
        g_h4[(size_t)(row0 + r) * 4 + c] = acc;
    }
}

// ---------------- instance norm (per-channel over nodes) ----------------
__global__ void k_zero_stats() { g_stats[threadIdx.x] = 0.0f; }
__global__ void k_in_stats(const float* __restrict__ x) {
    int c = threadIdx.x;
    float s = 0.0f, q = 0.0f;
    for (int r = blockIdx.x; r < NN; r += gridDim.x) {
        float v = x[(size_t)r * HH + c];
        s += v; q += v * v;
    }
    atomicAdd(&g_stats[c], s);
    atomicAdd(&g_stats[HH + c], q);
}
__global__ void k_in_apply(float* __restrict__ x) {
    int idx = blockIdx.x * blockDim.x + threadIdx.x;
    if (idx >= NN * HH) return;
    int c = idx & (HH - 1);
    const float invn = 1.0f / (float)NN;
    float m = g_stats[c] * invn;
    float var = g_stats[HH + c] * invn - m * m;
    x[idx] = (x[idx] - m) * rsqrtf(var + EPSF);
}

// ---------------- recurrent step tail ----------------
__global__ void k_copyF0(const float* __restrict__ F0) {
    int i = blockIdx.x * blockDim.x + threadIdx.x;
    if (i < NN * NFF) g_F[i] = F0[i];
}
__global__ void k_step_final(const float* __restrict__ b9, float* __restrict__ out, int t) {
    int i = blockIdx.x * blockDim.x + threadIdx.x;
    if (i >= NN) return;
    float di = g_dinv[i];
    const float4* h4 = (const float4*)g_h4;
    float4 v = h4[i];
    float w = di * di;
    float a0 = b9[0] + w * v.x, a1 = b9[1] + w * v.y;
    float a2 = b9[2] + w * v.z, a3 = b9[3] + w * v.w;
    for (int e = g_rowptr[i]; e < g_rowptr[i + 1]; e++) {
        int s = g_src[e];
        float ww = g_dinv[s] * di;
        float4 u = h4[s];
        a0 += ww * u.x; a1 += ww * u.y; a2 += ww * u.z; a3 += ww * u.w;
    }
    float d0 = tanhf(a0), d1 = tanhf(a1), d2 = tanhf(a2), d3 = tanhf(a3);
    float4 f = ((float4*)g_F)[i];
    float n0 = tanhf(f.x + DTF * d0), n1 = tanhf(f.y + DTF * d1);
    float n2 = tanhf(f.z + DTF * d2), n3 = tanhf(f.w + DTF * d3);
    ((float4*)g_F)[i] = make_float4(n0, n1, n2, n3);
    int ob = i * TT * NFF + t * NFF;
    out[ob + 0] = n0; out[ob + 1] = n1; out[ob + 2] = n2; out[ob + 3] = n3;
    int ob2 = NN * TT * NFF + ob;
    out[ob2 + 0] = d0; out[ob2 + 1] = d1; out[ob2 + 2] = d2; out[ob2 + 3] = d3;
}

// ---------------- host orchestration ----------------
static void instnorm(float* x) {
    k_zero_stats<<<1, 2 * HH>>>();
    k_in_stats<<<512, HH>>>(x);
    k_in_apply<<<(NN * HH + 255) / 256, 256>>>(x);
}

extern "C" void kernel_launch(void* const* d_in, const int* in_sizes, int n_in,
                              void* d_out, int out_size) {
    const float* F0        = (const float*)d_in[0];
    const int*   ei        = (const int*)d_in[1];
    const float* meshfield = (const float*)d_in[2];
    int w = (n_in >= 16 && in_sizes[3] == 1) ? 4 : 3;  // skip scalar n_time if present
    const float* mesh_W0 = (const float*)d_in[w + 0];
    const float* mesh_b0 = (const float*)d_in[w + 1];
    const float* mesh_Wh = (const float*)d_in[w + 2];
    const float* mesh_bh = (const float*)d_in[w + 3];
    const float* mesh_W9 = (const float*)d_in[w + 4];
    const float* mesh_b9 = (const float*)d_in[w + 5];
    const float* diff_W0 = (const float*)d_in[w + 6];
    const float* diff_b0 = (const float*)d_in[w + 7];
    const float* diff_Wh = (const float*)d_in[w + 8];
    const float* diff_bh = (const float*)d_in[w + 9];
    const float* diff_W9 = (const float*)d_in[w + 10];
    const float* diff_b9 = (const float*)d_in[w + 11];
    float* out = (float*)d_out;

    float *px, *pz, *pxcat, *psmall;
    cudaGetSymbolAddress((void**)&px, g_x);
    cudaGetSymbolAddress((void**)&pz, g_z);
    cudaGetSymbolAddress((void**)&pxcat, g_xcat);
    cudaGetSymbolAddress((void**)&psmall, g_small);

    const int GB = (NN + 63) / 64;   // generic gemm blocks
    const int FB = (NN + BM - 1) / BM;  // fused blocks

    // --- graph normalization + CSR ---
    k_zero_cnt<<<(NN + 255) / 256, 256>>>();
    k_count<<<(EE + 255) / 256, 256>>>(ei);
    k_dinv<<<(NN + 255) / 256, 256>>>();
    k_scan<<<1, 1024>>>();
    k_fill<<<(EE + 255) / 256, 256>>>(ei);

    // --- mesh descriptor block ---
    k_agg8<<<(NN + 127) / 128, 128>>>(meshfield);                      // A@meshfield (8 cols)
    k_gemm128<0><<<GB, 256>>>(psmall, NMM, mesh_W0, mesh_b0, px);      // conv0
    instnorm(px);
    {
        float* cur = px; float* nxt = pz;
        for (int l = 0; l < DMID; l++) {
            k_fused<true, 0><<<FB, 256>>>(cur, mesh_Wh + (size_t)l * HH * HH,
                                          mesh_bh + (size_t)l * HH, nxt);
            float* t2 = cur; cur = nxt; nxt = t2;
        }
        // conv9 + tanh -> mesh latent in nxt
        k_fused<false, 1><<<FB, 256>>>(cur, mesh_W9, mesh_b9, nxt);
        k_agg128<false><<<NN, HH>>>(nxt, pxcat, KCAT, NFF);            // xcat[:,4:132] (time-invariant)
    }

    // --- recurrent differentiator ---
    k_copyF0<<<(NN * NFF + 255) / 256, 256>>>(F0);
    for (int t = 0; t < TT; t++) {
        k_aggF<<<(NN + 127) / 128, 128>>>();                           // xcat[:,0:4] = A@F
        k_gemm128<0><<<GB, 256>>>(pxcat, KCAT, diff_W0, diff_b0, px);  // conv0 (K=132)
        instnorm(px);
        float* cur = px; float* nxt = pz;
        for (int l = 0; l < DMID; l++) {
            k_fused<true, 0><<<FB, 256>>>(cur, diff_Wh + (size_t)l * HH * HH,
                                          diff_bh + (size_t)l * HH, nxt);
            float* t2 = cur; cur = nxt; nxt = t2;
        }
        k_gemm_to4<<<(NN + 31) / 32, 128>>>(cur, diff_W9);             // x @ W9 -> h4
        k_step_final<<<(NN + 127) / 128, 128>>>(diff_b9, out, t);      // A@h4+b9, tanh, Euler, write
    }
    (void)out_size;
}